// round 13
// baseline (speedup 1.0000x reference)
#include <cuda_runtime.h>

#define IN_F   4096
#define OUT_F  4096
#define RANK   8
#define MAX_TOKENS 8192

// Intermediate t[tok][r] = x @ core1^T  (256 KB, lives in L2)
__device__ float g_t[MAX_TOKENS * RANK];

// ---- packed f32x2 helpers (ptxas never auto-fuses; PTX-only path) ----------
__device__ __forceinline__ unsigned long long fma2(unsigned long long a,
                                                   unsigned long long b,
                                                   unsigned long long c) {
    unsigned long long d;
    asm("fma.rn.f32x2 %0, %1, %2, %3;" : "=l"(d) : "l"(a), "l"(b), "l"(c));
    return d;
}
__device__ __forceinline__ float2 unpack2(unsigned long long v) {
    float2 f;
    asm("mov.b64 {%0, %1}, %2;" : "=f"(f.x), "=f"(f.y) : "l"(v));
    return f;
}

// ---------------------------------------------------------------------------
// Stage 1: t[tok, r] = sum_i x[tok, i] * core1[r, i]
// ISSUE-PORT BOUND as scalar FFMA (42M warp-instrs = the invariant 41us).
// Fix: packed fma.rn.f32x2 halves FMA issue. Register-safe decomposition:
// 2 tokens/warp (acc = 16 u64 = 32 regs), full IN_F row, unroll 1 ->
// ~64 regs, 4 blocks/SM. Issue drops to ~20M instrs (~19us); memory floor
// (~26us for the 128MB x stream) becomes the limit.
// 256 thr = 8 warps = 16 tokens/block -> 512 blocks.
// ---------------------------------------------------------------------------
__global__ void __launch_bounds__(256) tt_stage1(const float* __restrict__ x,
                                                 const float* __restrict__ c1) {
    const int warp = threadIdx.x >> 5;
    const int lane = threadIdx.x & 31;
    const int token0 = blockIdx.x * 16 + warp * 2;

    const ulonglong2* xp = reinterpret_cast<const ulonglong2*>(x)
                         + (size_t)token0 * (IN_F / 4);
    const ulonglong2* cp = reinterpret_cast<const ulonglong2*>(c1);

    unsigned long long acc0[RANK], acc1[RANK];
#pragma unroll
    for (int r = 0; r < RANK; r++) { acc0[r] = 0ull; acc1[r] = 0ull; }

    // 1024 float4 (as ulonglong2) per token row, 32 lanes -> 32 iterations
#pragma unroll 1
    for (int i = lane; i < IN_F / 4; i += 32) {
        const ulonglong2 x0 = xp[i];                      // token 0
        const ulonglong2 x1 = xp[(IN_F / 4) + i];         // token 1
#pragma unroll
        for (int r = 0; r < RANK; r++) {
            const ulonglong2 c = __ldg(cp + (size_t)r * (IN_F / 4) + i);
            acc0[r] = fma2(x0.x, c.x, acc0[r]);
            acc0[r] = fma2(x0.y, c.y, acc0[r]);
            acc1[r] = fma2(x1.x, c.x, acc1[r]);
            acc1[r] = fma2(x1.y, c.y, acc1[r]);
        }
    }

#pragma unroll
    for (int r = 0; r < RANK; r++) {
        const float2 f0 = unpack2(acc0[r]);
        const float2 f1 = unpack2(acc1[r]);
        float v0 = f0.x + f0.y;
        float v1 = f1.x + f1.y;
#pragma unroll
        for (int off = 16; off; off >>= 1) {
            v0 += __shfl_xor_sync(0xffffffffu, v0, off);
            v1 += __shfl_xor_sync(0xffffffffu, v1, off);
        }
        if (lane == 0) {
            g_t[(size_t)token0 * RANK + r]       = v0;
            g_t[(size_t)(token0 + 1) * RANK + r] = v1;
        }
    }
}

// ---------------------------------------------------------------------------
// Stage 2: y[tok, o] = bias[o] + sum_r t[tok, r] * core0[o, r]
// Best-known version (25.6-26.8us): 64 tokens x 1024 outputs per block,
// t via LDS.128 float4 pairs, c0 coeffs in regs, STG.128 evict-first.
// Write-path bound; f32x2 doesn't help here (verified rounds 3/4).
// ---------------------------------------------------------------------------
__global__ void __launch_bounds__(256) tt_stage2(const float* __restrict__ c0,
                                                 const float* __restrict__ bias,
                                                 float* __restrict__ y) {
    __shared__ float4 ts[64 * 2];                 // t[64][8] as float4 pairs
    const int tid = threadIdx.x;
    const int token0 = blockIdx.y * 64;
    const int o = blockIdx.x * 1024 + tid * 4;

    if (tid < 128) {
        const float4* tg = reinterpret_cast<const float4*>(g_t + (size_t)token0 * RANK);
        ts[tid] = tg[tid];
    }

    float4 ca[4], cb[4];
#pragma unroll
    for (int j = 0; j < 4; j++) {
        const float4* c = reinterpret_cast<const float4*>(c0 + (size_t)(o + j) * RANK);
        ca[j] = __ldg(c);
        cb[j] = __ldg(c + 1);
    }
    const float4 bv = __ldg(reinterpret_cast<const float4*>(bias + o));

    __syncthreads();

#pragma unroll 4
    for (int tok = 0; tok < 64; tok++) {
        const float4 tA = ts[tok * 2];
        const float4 tB = ts[tok * 2 + 1];

        float4 res;
        res.x = bv.x + ca[0].x * tA.x + ca[0].y * tA.y + ca[0].z * tA.z + ca[0].w * tA.w
                     + cb[0].x * tB.x + cb[0].y * tB.y + cb[0].z * tB.z + cb[0].w * tB.w;
        res.y = bv.y + ca[1].x * tA.x + ca[1].y * tA.y + ca[1].z * tA.z + ca[1].w * tA.w
                     + cb[1].x * tB.x + cb[1].y * tB.y + cb[1].z * tB.z + cb[1].w * tB.w;
        res.z = bv.z + ca[2].x * tA.x + ca[2].y * tA.y + ca[2].z * tA.z + ca[2].w * tA.w
                     + cb[2].x * tB.x + cb[2].y * tB.y + cb[2].z * tB.z + cb[2].w * tB.w;
        res.w = bv.w + ca[3].x * tA.x + ca[3].y * tA.y + ca[3].z * tA.z + ca[3].w * tA.w
                     + cb[3].x * tB.x + cb[3].y * tB.y + cb[3].z * tB.z + cb[3].w * tB.w;

        __stcs(reinterpret_cast<float4*>(y + (size_t)(token0 + tok) * OUT_F + o),
               res);
    }
}

extern "C" void kernel_launch(void* const* d_in, const int* in_sizes, int n_in,
                              void* d_out, int out_size) {
    const float* x    = (const float*)d_in[0];   // [TOKENS, IN_F]
    const float* c0   = (const float*)d_in[1];   // [OUT_F, RANK]
    const float* c1   = (const float*)d_in[2];   // [RANK, IN_F]
    const float* bias = (const float*)d_in[3];   // [OUT_F]
    float* y = (float*)d_out;

    const int tokens = in_sizes[0] / IN_F;       // 8192

    // Stage 1: 16 tokens/block (8 warps x 2 tokens), 512 blocks
    tt_stage1<<<tokens / 16, 256>>>(x, c1);

    // Stage 2: 4 output chunks x 64-token groups = 512 blocks
    dim3 g2(OUT_F / 1024, tokens / 64);
    tt_stage2<<<g2, 256>>>(c0, bias, y);
}

// round 14
// speedup vs baseline: 1.4361x; 1.4361x over previous
#include <cuda_runtime.h>
#include <stdint.h>

#define IN_F   4096
#define OUT_F  4096
#define RANK   8
#define MAX_TOKENS 8192
#define KSPLIT 8
#define KRANGE (IN_F / KSPLIT)     // 512 per warp
#define NCHUNK_K (KRANGE / 32)     // 16 k32 chunks

// Partial t per K-split slot; stage2 sums the 8 partials. (+ tf32 c1 copies)
__device__ float    g_part[KSPLIT][MAX_TOKENS * RANK];   // 2 MB
__device__ uint32_t g_c1hi[IN_F * RANK];                 // c1^T as tf32 hi
__device__ uint32_t g_c1lo[IN_F * RANK];                 // c1^T as tf32 lo

__device__ __forceinline__ uint32_t f2tf32(float v) {
    uint32_t r;
    asm("cvt.rna.tf32.f32 %0, %1;" : "=r"(r) : "f"(v));
    return r;
}

// D += A*B, m16n8k8 tf32. In-place accumulate.
__device__ __forceinline__ void mma_tf32(float acc[4], const uint32_t a[4],
                                         const uint32_t b[2]) {
    asm("mma.sync.aligned.m16n8k8.row.col.f32.tf32.tf32.f32 "
        "{%0,%1,%2,%3},{%4,%5,%6,%7},{%8,%9},{%0,%1,%2,%3};"
        : "+f"(acc[0]), "+f"(acc[1]), "+f"(acc[2]), "+f"(acc[3])
        : "r"(a[0]), "r"(a[1]), "r"(a[2]), "r"(a[3]),
          "r"(b[0]), "r"(b[1]));
}

// ---------------------------------------------------------------------------
// Prep: c1[r][i] -> transposed tf32 hi/lo arrays c1t[i][r]. 32K elems, ~2us.
// ---------------------------------------------------------------------------
__global__ void __launch_bounds__(256) tt_prep(const float* __restrict__ c1) {
    const int idx = blockIdx.x * 256 + threadIdx.x;   // = i*8 + r
    const int i = idx >> 3, r = idx & 7;
    const float v = c1[(size_t)r * IN_F + i];
    const uint32_t hi = f2tf32(v);
    g_c1hi[idx] = hi;
    g_c1lo[idx] = f2tf32(v - __uint_as_float(hi));
}

// ---------------------------------------------------------------------------
// Stage 1 (tensor): t[tok, r] = sum_i x[tok,i] * c1[r,i] via m16n8k8 tf32.
// Block = 256 thr = 8 warps = ONE 16-token tile; warp w owns K-range
// [w*512,(w+1)*512). x staged in k32 chunks to smem (rows padded to 36
// floats: bank = (4g+tig+koff) mod 32, provably conflict-free for the A
// fragment). x split hi/lo in-register; 3 MMAs/k8-step (AhiBhi+AhiBlo+AloBhi)
// -> residual ~2^-22. A-frag (PTX ISA): a0=(g,tig) a1=(g+8,tig) a2=(g,tig+4)
// a3=(g+8,tig+4); B-frag col: b0=(k=tig,n=g) b1=(k=tig+4,n=g);
// C: c0=(g,2tig) c1=(g,2tig+1) c2=(g+8,2tig) c3=(g+8,2tig+1).
// ---------------------------------------------------------------------------
__global__ void __launch_bounds__(256) tt_stage1(const float* __restrict__ x) {
    __shared__ float xs[KSPLIT][16 * 36];     // 18 KB, per-warp k32 tiles

    const int w    = threadIdx.x >> 5;        // warp = K-split slot
    const int lane = threadIdx.x & 31;
    const int g    = lane >> 2;               // 0..7
    const int tig  = lane & 3;                // 0..3
    const int token0 = blockIdx.x * 16;
    const int k0 = w * KRANGE;

    float* xw = xs[w];
    const int srow = lane >> 1;               // staging row 0..15
    const int sj   = (lane & 1) * 4;          // staging float4 base 0 or 4

    const float4* xg = reinterpret_cast<const float4*>(x);

    // prefetch chunk 0
    float4 ld0, ld1, ld2, ld3;
    {
        const size_t base = (size_t)(token0 + srow) * (IN_F / 4) + (k0 >> 2) + sj;
        ld0 = xg[base]; ld1 = xg[base + 1]; ld2 = xg[base + 2]; ld3 = xg[base + 3];
    }

    float acc[4] = {0.f, 0.f, 0.f, 0.f};

    for (int c = 0; c < NCHUNK_K; c++) {
        // deposit staged chunk (rows of 36 floats; 16B-aligned float4 stores)
        float4* dst = reinterpret_cast<float4*>(xw + srow * 36 + sj * 4);
        dst[0] = ld0; dst[1] = ld1; dst[2] = ld2; dst[3] = ld3;
        __syncwarp();

        if (c + 1 < NCHUNK_K) {               // prefetch next chunk
            const size_t base = (size_t)(token0 + srow) * (IN_F / 4)
                              + ((k0 + (c + 1) * 32) >> 2) + sj;
            ld0 = xg[base]; ld1 = xg[base + 1]; ld2 = xg[base + 2]; ld3 = xg[base + 3];
        }

        const int kc = k0 + c * 32;
#pragma unroll
        for (int ks = 0; ks < 4; ks++) {
            const int koff = ks * 8;
            // A fragment from smem (conflict-free LDS.32)
            const float r0 = xw[g * 36 + koff + tig];
            const float r1 = xw[(g + 8) * 36 + koff + tig];
            const float r2 = xw[g * 36 + koff + tig + 4];
            const float r3 = xw[(g + 8) * 36 + koff + tig + 4];

            uint32_t ahi[4], alo[4];
            ahi[0] = f2tf32(r0); ahi[1] = f2tf32(r1);
            ahi[2] = f2tf32(r2); ahi[3] = f2tf32(r3);
            alo[0] = f2tf32(r0 - __uint_as_float(ahi[0]));
            alo[1] = f2tf32(r1 - __uint_as_float(ahi[1]));
            alo[2] = f2tf32(r2 - __uint_as_float(ahi[2]));
            alo[3] = f2tf32(r3 - __uint_as_float(ahi[3]));

            // B fragment from transposed tf32 c1 (contiguous 128B per instr)
            const int bi0 = (kc + koff + tig) * RANK + g;
            const int bi1 = (kc + koff + tig + 4) * RANK + g;
            const uint32_t bhi[2] = { __ldg(&g_c1hi[bi0]), __ldg(&g_c1hi[bi1]) };
            const uint32_t blo[2] = { __ldg(&g_c1lo[bi0]), __ldg(&g_c1lo[bi1]) };

            mma_tf32(acc, ahi, bhi);
            mma_tf32(acc, ahi, blo);
            mma_tf32(acc, alo, bhi);
        }
        __syncwarp();
    }

    // Partials: (c0,c1)->row g ranks 2tig,2tig+1; (c2,c3)->row g+8. STG.64.
    float2* gp = reinterpret_cast<float2*>(&g_part[w][0]);
    gp[((size_t)(token0 + g) * RANK + 2 * tig) >> 1]     = make_float2(acc[0], acc[1]);
    gp[((size_t)(token0 + g + 8) * RANK + 2 * tig) >> 1] = make_float2(acc[2], acc[3]);
}

// ---------------------------------------------------------------------------
// Stage 2: y[tok, o] = bias[o] + sum_r t[tok, r] * core0[o, r]
// Best-known body (25.6us): 64 tokens x 1024 outputs per block, t via
// LDS.128 float4 pairs; smem tile = fixed-order sum of the 8 K-partials.
// ---------------------------------------------------------------------------
__global__ void __launch_bounds__(256) tt_stage2(const float* __restrict__ c0,
                                                 const float* __restrict__ bias,
                                                 float* __restrict__ y) {
    __shared__ float4 ts[64 * 2];
    const int tid = threadIdx.x;
    const int token0 = blockIdx.y * 64;
    const int o = blockIdx.x * 1024 + tid * 4;

    if (tid < 128) {
        const size_t base = (size_t)token0 * RANK / 4;   // float4 units
        float4 s = make_float4(0.f, 0.f, 0.f, 0.f);
#pragma unroll
        for (int p = 0; p < KSPLIT; p++) {
            const float4 v = reinterpret_cast<const float4*>(g_part[p])[base + tid];
            s.x += v.x; s.y += v.y; s.z += v.z; s.w += v.w;
        }
        ts[tid] = s;
    }

    float4 ca[4], cb[4];
#pragma unroll
    for (int j = 0; j < 4; j++) {
        const float4* c = reinterpret_cast<const float4*>(c0 + (size_t)(o + j) * RANK);
        ca[j] = __ldg(c);
        cb[j] = __ldg(c + 1);
    }
    const float4 bv = __ldg(reinterpret_cast<const float4*>(bias + o));

    __syncthreads();

#pragma unroll 4
    for (int tok = 0; tok < 64; tok++) {
        const float4 tA = ts[tok * 2];
        const float4 tB = ts[tok * 2 + 1];

        float4 res;
        res.x = bv.x + ca[0].x * tA.x + ca[0].y * tA.y + ca[0].z * tA.z + ca[0].w * tA.w
                     + cb[0].x * tB.x + cb[0].y * tB.y + cb[0].z * tB.z + cb[0].w * tB.w;
        res.y = bv.y + ca[1].x * tA.x + ca[1].y * tA.y + ca[1].z * tA.z + ca[1].w * tA.w
                     + cb[1].x * tB.x + cb[1].y * tB.y + cb[1].z * tB.z + cb[1].w * tB.w;
        res.z = bv.z + ca[2].x * tA.x + ca[2].y * tA.y + ca[2].z * tA.z + ca[2].w * tA.w
                     + cb[2].x * tB.x + cb[2].y * tB.y + cb[2].z * tB.z + cb[2].w * tB.w;
        res.w = bv.w + ca[3].x * tA.x + ca[3].y * tA.y + ca[3].z * tA.z + ca[3].w * tA.w
                     + cb[3].x * tB.x + cb[3].y * tB.y + cb[3].z * tB.z + cb[3].w * tB.w;

        __stcs(reinterpret_cast<float4*>(y + (size_t)(token0 + tok) * OUT_F + o),
               res);
    }
}

extern "C" void kernel_launch(void* const* d_in, const int* in_sizes, int n_in,
                              void* d_out, int out_size) {
    const float* x    = (const float*)d_in[0];   // [TOKENS, IN_F]
    const float* c0   = (const float*)d_in[1];   // [OUT_F, RANK]
    const float* c1   = (const float*)d_in[2];   // [RANK, IN_F]
    const float* bias = (const float*)d_in[3];   // [OUT_F]
    float* y = (float*)d_out;

    const int tokens = in_sizes[0] / IN_F;       // 8192

    // c1 -> transposed tf32 hi/lo (32K elems)
    tt_prep<<<(IN_F * RANK) / 256, 256>>>(c1);

    // Stage 1: one 16-token tile per block, 8 K-split warps -> 512 blocks
    tt_stage1<<<tokens / 16, 256>>>(x);

    // Stage 2: 4 output chunks x 64-token groups = 512 blocks
    dim3 g2(OUT_F / 1024, tokens / 64);
    tt_stage2<<<g2, 256>>>(c0, bias, y);
}